// round 16
// baseline (speedup 1.0000x reference)
#include <cuda_runtime.h>
#include <cstdint>

// Problem: x[S,B,I] fp32, W[I,4H], U[H,4H], bias[4H]; S=2048,B=64,I=H=512
#define S_LEN 2048
#define NB 64
#define NI 512
#define NH 512
#define NCTA 128           // <= SM count -> all resident, grid barrier safe
#define NTHR 512           // 16 warps = 4 per SMSP (latency hiding)
#define NWARP 16
#define GC 16              // gate columns per CTA (4 h-cols x 4 gates)
#define JPC 4
#define CHUNK 128
#define NCHUNK 8
#define KSLICE 8           // k per warp per chunk (128 / 16 warps)
#define ZSTRIDE 68         // floats per k-row (64 + 4 pad: bank rotation)
#define ZBUF (CHUNK * ZSTRIDE)      // 8704 floats per z buffer
#define RSTRIDE 66         // reduction: 64 rows + 2 pad
#define RWARP (GC * RSTRIDE)        // 1056 floats per warp partition

// shared layout (floats)
#define WSM_OFF 0                                  // 1024 x 16 = 16384
#define ZSM_OFF 16384                              // 2 x 8704 = 17408
#define RED_OFF (ZSM_OFF + 2 * ZBUF)               // 33792; 16 x 1056 = 16896
#define BIAS_OFF (RED_OFF + NWARP * RWARP)         // 50688
#define SMEM_FLOATS (BIAS_OFF + 16)                // 50704
#define SMEM_BYTES (SMEM_FLOATS * 4)               // 202816 B (< 227KB cap)

__device__ unsigned g_bar_count;
__device__ unsigned g_bar_gen;

__device__ __forceinline__ uint64_t pack2(float a, float b) {
    uint64_t r;
    asm("mov.b64 %0, {%1, %2};" : "=l"(r) : "f"(a), "f"(b));
    return r;
}
__device__ __forceinline__ float2 unpack2(uint64_t v) {
    float2 f;
    asm("mov.b64 {%0, %1}, %2;" : "=f"(f.x), "=f"(f.y) : "l"(v));
    return f;
}
#define FFMA2(d, a, b) asm("fma.rn.f32x2 %0, %1, %2, %0;" : "+l"(d) : "l"(a), "l"(b))

__device__ __forceinline__ void grid_sync() {
    __threadfence();
    __syncthreads();
    if (threadIdx.x == 0) {
        unsigned g = *(volatile unsigned*)&g_bar_gen;
        if (atomicAdd(&g_bar_count, 1u) == gridDim.x - 1u) {
            atomicExch(&g_bar_count, 0u);
            __threadfence();
            atomicExch(&g_bar_gen, g + 1u);
        } else {
            while (*(volatile unsigned*)&g_bar_gen == g) { __nanosleep(32); }
        }
        __threadfence();
    }
    __syncthreads();
}

// Stage one chunk: thread owns column kk, 16 b-rows (b0 = 16i + 4*bq).
// Warp lanes have consecutive kk -> each scalar LDG is a coalesced 128B line.
__device__ __forceinline__ void stage_load(float4 v[4], const float* __restrict__ src,
                                           int kk, int bq) {
#pragma unroll
    for (int i = 0; i < 4; i++) {
        int b0 = 16 * i + 4 * bq;
        v[i].x = src[(b0 + 0) * 512 + kk];
        v[i].y = src[(b0 + 1) * 512 + kk];
        v[i].z = src[(b0 + 2) * 512 + kk];
        v[i].w = src[(b0 + 3) * 512 + kk];
    }
}

// Per-warp compute over its 8-k slice of the chunk.
// Lane tile: 16 rows (as 8 row-pairs, native f32x2 from ld.shared.v2.b64) x 2 cols.
// z-loads broadcast across the 8 col-lanes; w-load broadcast across the 4 row-groups.
__device__ __forceinline__ void compute_chunk(uint32_t zsa, const float* __restrict__ wbase,
                                              uint64_t acc[4][2][2], int wq0, int rg, int cg) {
#pragma unroll
    for (int q = 0; q < KSLICE; q++) {
        int kk = wq0 + q;
        uint32_t za = zsa + (uint32_t)((kk * ZSTRIDE + rg * 4) * 4);
        uint64_t za0, zb0, za1, zb1, za2, zb2, za3, zb3;
        asm volatile("ld.shared.v2.u64 {%0,%1},[%2];" : "=l"(za0), "=l"(zb0) : "r"(za));
        asm volatile("ld.shared.v2.u64 {%0,%1},[%2];" : "=l"(za1), "=l"(zb1) : "r"(za + 64u));
        asm volatile("ld.shared.v2.u64 {%0,%1},[%2];" : "=l"(za2), "=l"(zb2) : "r"(za + 128u));
        asm volatile("ld.shared.v2.u64 {%0,%1},[%2];" : "=l"(za3), "=l"(zb3) : "r"(za + 192u));
        float2 wv = *(const float2*)(wbase + kk * GC + cg * 2);
        uint64_t wlo = pack2(wv.x, wv.x);
        uint64_t whi = pack2(wv.y, wv.y);
        FFMA2(acc[0][0][0], za0, wlo); FFMA2(acc[0][0][1], za0, whi);
        FFMA2(acc[0][1][0], zb0, wlo); FFMA2(acc[0][1][1], zb0, whi);
        FFMA2(acc[1][0][0], za1, wlo); FFMA2(acc[1][0][1], za1, whi);
        FFMA2(acc[1][1][0], zb1, wlo); FFMA2(acc[1][1][1], zb1, whi);
        FFMA2(acc[2][0][0], za2, wlo); FFMA2(acc[2][0][1], za2, whi);
        FFMA2(acc[2][1][0], zb2, wlo); FFMA2(acc[2][1][1], zb2, whi);
        FFMA2(acc[3][0][0], za3, wlo); FFMA2(acc[3][0][1], za3, whi);
        FFMA2(acc[3][1][0], zb3, wlo); FFMA2(acc[3][1][1], zb3, whi);
    }
}

__global__ void __launch_bounds__(NTHR, 1)
lstm_persist_kernel(const float* __restrict__ x, const float* __restrict__ W,
                    const float* __restrict__ U, const float* __restrict__ bias,
                    float* out, long long out_elems)
{
    extern __shared__ float sm[];
    float* Wsm    = sm + WSM_OFF;
    float* zsm    = sm + ZSM_OFF;
    float* redsm  = sm + RED_OFF;
    float* biassm = sm + BIAS_OFF;

    const int tid = threadIdx.x;
    const int j0  = blockIdx.x * JPC;

    // one-time: [W;U] slice (1024 x 16) + bias into smem
#pragma unroll 4
    for (int i = 0; i < 32; i++) {
        int idx = i * NTHR + tid;
        int k = idx >> 4;
        int c = idx & 15;
        int G = (c >> 2) * NH + j0 + (c & 3);
        float v = (k < NI) ? W[k * (4 * NH) + G] : U[(k - NI) * (4 * NH) + G];
        Wsm[k * GC + c] = v;
    }
    if (tid < GC) biassm[tid] = bias[(tid >> 2) * NH + j0 + (tid & 3)];
    __syncthreads();

    // compute decomposition: warp = one of 16 K partitions (8 k each)
    const int w    = tid >> 5;
    const int lane = tid & 31;
    const int rg   = lane >> 3;         // row group: rows [rg*16, rg*16+16)
    const int cg   = lane & 7;          // col group: cols cg*2, cg*2+1
    const int wq0  = w * KSLICE;
    // staging decomposition
    const int kk_s = tid & 127;
    const int bq   = tid >> 7;          // 0..3
    // epilogue decomposition (threads < 256 only)
    const int eb  = (tid & 255) >> 2;
    const int edj = tid & 3;

    uint32_t z0_sa = (uint32_t)__cvta_generic_to_shared(zsm);
    uint32_t z1_sa = z0_sa + (uint32_t)(ZBUF * 4);

    float creg = 0.f, hlast = 0.f;
    float4 v[4];

    // preload t=0, chunk 0 (x part)
    stage_load(v, x, kk_s, bq);

    for (int t = 0; t < S_LEN; t++) {
        uint64_t acc[4][2][2];
#pragma unroll
        for (int a = 0; a < 4; a++)
#pragma unroll
            for (int b = 0; b < 2; b++) { acc[a][b][0] = 0ull; acc[a][b][1] = 0ull; }

        const float* xt = x + (size_t)t * NB * NI;
        const float* hp = out + (size_t)(t - 1) * NB * NH;   // valid for t>0

#pragma unroll 1
        for (int ch = 0; ch < NCHUNK; ch++) {
            float*   zb  = (ch & 1) ? (zsm + ZBUF) : zsm;
            uint32_t zsa = (ch & 1) ? z1_sa : z0_sa;

            // store staged regs: slot = 16*bq + 4*i  (bit-swap b[3:2]<->b[5:4];
            // stride-68 rotation => conflict-free 4-phase STS.128)
#pragma unroll
            for (int i = 0; i < 4; i++) {
                int b0 = 16 * i + 4 * bq;
                int slot = ((b0 & 12) << 2) | ((b0 >> 2) & 12);
                *(float4*)&zb[kk_s * ZSTRIDE + slot] = v[i];
            }
            __syncthreads();

            // prefetch next chunk while computing this one
            if (ch < NCHUNK - 1) {
                int nc = ch + 1;
                if (nc < 4) {
                    stage_load(v, xt + nc * CHUNK, kk_s, bq);
                } else if (t == 0) {
#pragma unroll
                    for (int i = 0; i < 4; i++) v[i] = make_float4(0.f, 0.f, 0.f, 0.f);
                } else {
                    stage_load(v, hp + (nc - 4) * CHUNK, kk_s, bq);
                }
            }

            compute_chunk(zsa, Wsm + ch * CHUNK * GC, acc, wq0, rg, cg);
        }

        // reduction: per-warp partials, transposed [w][col][row], row-pairs as STS.64
#pragma unroll
        for (int vv = 0; vv < 4; vv++)
#pragma unroll
            for (int h = 0; h < 2; h++)
#pragma unroll
                for (int c = 0; c < 2; c++) {
                    float2 f = unpack2(acc[vv][h][c]);
                    int row = rg * 16 + vv * 4 + h * 2;
                    int col = cg * 2 + c;
                    *(float2*)&redsm[w * RWARP + col * RSTRIDE + row] = f;
                }
        __syncthreads();

        // epilogue: thread owns (eb, edj); sum 16 warp-partials per gate
        if (tid < 256) {
            float gs[4];
#pragma unroll
            for (int g = 0; g < 4; g++) {
                int c = (g << 2) + edj;
                float s = biassm[c];
#pragma unroll
                for (int p = 0; p < NWARP; p++) s += redsm[p * RWARP + c * RSTRIDE + eb];
                gs[g] = s;
            }
            float it = 1.f / (1.f + __expf(-gs[0]));
            float ft = 1.f / (1.f + __expf(-gs[1]));
            float gt = tanhf(gs[2]);
            float ot = 1.f / (1.f + __expf(-gs[3]));
            creg = ft * creg + it * gt;
            float hv = ot * tanhf(creg);
            hlast = hv;
            out[(size_t)t * NB * NH + (size_t)eb * NH + j0 + edj] = hv;
        }

        // prefetch next step's first x chunk before the barrier (pure overlap)
        if (t < S_LEN - 1) stage_load(v, x + (size_t)(t + 1) * NB * NI, kk_s, bq);

        grid_sync();
    }

    // optional tail: (h_T, c_T) after hidden_seq if out has room
    if (tid < 256) {
        long long base = (long long)S_LEN * NB * NH;
        long long bh   = (long long)NB * NH;
        if (base + bh <= out_elems)
            out[base + (size_t)eb * NH + j0 + edj] = hlast;
        if (base + 2 * bh <= out_elems)
            out[base + bh + (size_t)eb * NH + j0 + edj] = creg;
    }
}

extern "C" void kernel_launch(void* const* d_in, const int* in_sizes, int n_in,
                              void* d_out, int out_size) {
    (void)in_sizes; (void)n_in;
    const float* x    = (const float*)d_in[0];
    const float* W    = (const float*)d_in[1];
    const float* U    = (const float*)d_in[2];
    const float* bias = (const float*)d_in[3];
    float* out = (float*)d_out;

    cudaFuncSetAttribute(lstm_persist_kernel,
                         cudaFuncAttributeMaxDynamicSharedMemorySize, SMEM_BYTES);
    lstm_persist_kernel<<<NCTA, NTHR, SMEM_BYTES>>>(x, W, U, bias, out,
                                                    (long long)out_size);
}